// round 9
// baseline (speedup 1.0000x reference)
#include <cuda_runtime.h>
#include <cuda_bf16.h>
#include <cuda_device_runtime_api.h>

// y[n] = beta_0 + sum_{i<7,j<64} x[n,i,j] * w[i,j],  w = gamma^T @ alpha (rank 64)
// x: [131072, 7, 64] fp32. HBM-bound: 235 MB read -> ~34us kernel floor.
// prep: 7 blocks x 64 threads, PDL trigger first; main: PDL secondary that
// issues its 7 x-loads before griddepcontrol.wait.
// R9 delta vs R8: __launch_bounds__(256, 6) to cap regs (~42) and raise
// resident warps 40 -> 48/SM; occupancy was marginally binding at DRAM 80.7%.

#define N_GAMMA 7
#define N_ALPHA 64
#define RANK    64
#define W_ELEMS (N_GAMMA * N_ALPHA)   // 448
#define W_F4    (W_ELEMS / 4)         // 112
#define ROWS_PER_WARP 2
#define WARPS_PER_BLOCK 8

__device__ float g_w[W_ELEMS];

// Block i computes w[i][0..63]; thread j computes one element.
__global__ void prep_w_kernel(const float* __restrict__ gamma,   // [64,7]
                              const float* __restrict__ alpha)   // [64,64]
{
    cudaTriggerProgrammaticLaunchCompletion();

    int i = blockIdx.x;    // 0..6
    int j = threadIdx.x;   // 0..63
    float s = 0.0f;
#pragma unroll
    for (int r = 0; r < RANK; r++)
        s = fmaf(gamma[r * N_GAMMA + i], alpha[r * N_ALPHA + j], s);
    g_w[i * N_ALPHA + j] = s;
}

__device__ __forceinline__ float fma4(float acc, float4 v, float4 w) {
    acc = fmaf(v.x, w.x, acc);
    acc = fmaf(v.y, w.y, acc);
    acc = fmaf(v.z, w.z, acc);
    acc = fmaf(v.w, w.w, acc);
    return acc;
}

__global__ __launch_bounds__(256, 6) void cp_dot_kernel(
    const float* __restrict__ x,
    const float* __restrict__ beta0_p,
    float* __restrict__ y,
    int n_rows)
{
    __shared__ float4 sw[W_F4];

    int warp = threadIdx.x >> 5;
    int lane = threadIdx.x & 31;
    int n0 = (blockIdx.x * WARPS_PER_BLOCK + warp) * ROWS_PER_WARP;

    // --- Issue x loads FIRST: independent of prep kernel's w. ---
    float4 v0, v1, v2, v3, v4, v5, v6;
    bool active = (n0 < n_rows);
    if (active) {
        const float4* xr = reinterpret_cast<const float4*>(x + (size_t)n0 * W_ELEMS);
        v0 = xr[lane];
        v1 = xr[lane + 32];
        v2 = xr[lane + 64];
        v3 = xr[lane + 96];
        v4 = xr[lane + 128];
        v5 = xr[lane + 160];
        v6 = xr[lane + 192];
    }

    // --- Wait for prep kernel's writes (PDL); then stage w. ---
    cudaGridDependencySynchronize();

    const float4* wg4 = reinterpret_cast<const float4*>(g_w);
    if (threadIdx.x < W_F4)
        sw[threadIdx.x] = wg4[threadIdx.x];
    __syncthreads();

    if (!active) return;

    // w4 index = (lane + 32t) % 112 ; element belongs to row A if (lane+32t) < 112.
    float accA = 0.f, accB = 0.f;
    accA = fma4(accA, v0, sw[lane]);
    accA = fma4(accA, v1, sw[lane + 32]);
    accA = fma4(accA, v2, sw[lane + 64]);
    {   // t=3: lanes 0-15 -> row A (w idx lane+96); lanes 16-31 -> row B (w idx lane-16)
        float4 w3 = sw[(lane < 16) ? (lane + 96) : (lane - 16)];
        float d = fma4(0.f, v3, w3);
        if (lane < 16) accA += d; else accB += d;
    }
    accB = fma4(accB, v4, sw[lane + 16]);
    accB = fma4(accB, v5, sw[lane + 48]);
    accB = fma4(accB, v6, sw[lane + 80]);

    // Two interleaved butterfly reductions.
#pragma unroll
    for (int o = 16; o > 0; o >>= 1) {
        accA += __shfl_xor_sync(0xFFFFFFFFu, accA, o);
        accB += __shfl_xor_sync(0xFFFFFFFFu, accB, o);
    }

    if (lane < ROWS_PER_WARP && n0 + lane < n_rows) {
        float r = (lane == 0) ? accA : accB;
        y[n0 + lane] = beta0_p[0] + r;
    }
}

extern "C" void kernel_launch(void* const* d_in, const int* in_sizes, int n_in,
                              void* d_out, int out_size)
{
    const float* x     = (const float*)d_in[0];
    const float* beta0 = (const float*)d_in[1];
    const float* gamma = (const float*)d_in[2];
    const float* alpha = (const float*)d_in[3];
    float* y = (float*)d_out;

    int n_rows = in_sizes[0] / W_ELEMS;

    prep_w_kernel<<<N_GAMMA, N_ALPHA>>>(gamma, alpha);

    int rows_per_block = WARPS_PER_BLOCK * ROWS_PER_WARP;  // 16
    int grid = (n_rows + rows_per_block - 1) / rows_per_block;

    cudaLaunchConfig_t cfg = {};
    cfg.gridDim  = dim3(grid, 1, 1);
    cfg.blockDim = dim3(256, 1, 1);
    cfg.dynamicSmemBytes = 0;
    cfg.stream = 0;
    cudaLaunchAttribute attrs[1];
    attrs[0].id = cudaLaunchAttributeProgrammaticStreamSerialization;
    attrs[0].val.programmaticStreamSerializationAllowed = 1;
    cfg.attrs = attrs;
    cfg.numAttrs = 1;

    cudaError_t err = cudaLaunchKernelEx(&cfg, cp_dot_kernel, x, beta0, y, n_rows);
    if (err != cudaSuccess) {
        cp_dot_kernel<<<grid, 256>>>(x, beta0, y, n_rows);
    }
}

// round 10
// speedup vs baseline: 1.1532x; 1.1532x over previous
#include <cuda_runtime.h>
#include <cuda_bf16.h>
#include <cuda_device_runtime_api.h>

// y[n] = beta_0 + sum_{i<7,j<64} x[n,i,j] * w[i,j],  w = gamma^T @ alpha (rank 64)
// x: [131072, 7, 64] fp32. HBM-bound: 235 MB read.
// prep: 7 blocks x 64 threads, PDL trigger first-statement.
// main: PDL secondary. R10 delta vs R8: only 4 of 7 x-loads are issued before
// griddepcontrol.wait (16 payload regs live across it instead of 28); the
// remaining 3 issue right after the wait, their latency hidden by w staging.
// Goal: natural reg count ~40-44 (no forced cap -> no spills), occ up,
// DRAM% 80.7 -> ~84.

#define N_GAMMA 7
#define N_ALPHA 64
#define RANK    64
#define W_ELEMS (N_GAMMA * N_ALPHA)   // 448
#define W_F4    (W_ELEMS / 4)         // 112
#define ROWS_PER_WARP 2
#define WARPS_PER_BLOCK 8

__device__ float g_w[W_ELEMS];

// Block i computes w[i][0..63]; thread j computes one element.
__global__ void prep_w_kernel(const float* __restrict__ gamma,   // [64,7]
                              const float* __restrict__ alpha)   // [64,64]
{
    cudaTriggerProgrammaticLaunchCompletion();

    int i = blockIdx.x;    // 0..6
    int j = threadIdx.x;   // 0..63
    float s = 0.0f;
#pragma unroll
    for (int r = 0; r < RANK; r++)
        s = fmaf(gamma[r * N_GAMMA + i], alpha[r * N_ALPHA + j], s);
    g_w[i * N_ALPHA + j] = s;
}

__device__ __forceinline__ float fma4(float acc, float4 v, float4 w) {
    acc = fmaf(v.x, w.x, acc);
    acc = fmaf(v.y, w.y, acc);
    acc = fmaf(v.z, w.z, acc);
    acc = fmaf(v.w, w.w, acc);
    return acc;
}

__global__ __launch_bounds__(256) void cp_dot_kernel(
    const float* __restrict__ x,
    const float* __restrict__ beta0_p,
    float* __restrict__ y,
    int n_rows)
{
    __shared__ float4 sw[W_F4];

    int warp = threadIdx.x >> 5;
    int lane = threadIdx.x & 31;
    int n0 = (blockIdx.x * WARPS_PER_BLOCK + warp) * ROWS_PER_WARP;

    bool active = (n0 < n_rows);
    const float4* xr = reinterpret_cast<const float4*>(x + (size_t)n0 * W_ELEMS);

    // --- 4 x-loads BEFORE the wait (hide prep under wave-1 DRAM latency). ---
    float4 v0, v1, v2, v3;
    if (active) {
        v0 = xr[lane];
        v1 = xr[lane + 32];
        v2 = xr[lane + 64];
        v3 = xr[lane + 96];
    }

    // --- Wait for prep kernel's writes (PDL). ---
    cudaGridDependencySynchronize();

    // --- Remaining 3 loads issue now; their latency hides under w staging. ---
    float4 v4, v5, v6;
    if (active) {
        v4 = xr[lane + 128];
        v5 = xr[lane + 160];
        v6 = xr[lane + 192];
    }

    const float4* wg4 = reinterpret_cast<const float4*>(g_w);
    if (threadIdx.x < W_F4)
        sw[threadIdx.x] = wg4[threadIdx.x];
    __syncthreads();

    if (!active) return;

    // w4 index = (lane + 32t) % 112 ; element belongs to row A if (lane+32t) < 112.
    float accA = 0.f, accB = 0.f;
    accA = fma4(accA, v0, sw[lane]);
    accA = fma4(accA, v1, sw[lane + 32]);
    accA = fma4(accA, v2, sw[lane + 64]);
    {   // t=3: lanes 0-15 -> row A (w idx lane+96); lanes 16-31 -> row B (w idx lane-16)
        float4 w3 = sw[(lane < 16) ? (lane + 96) : (lane - 16)];
        float d = fma4(0.f, v3, w3);
        if (lane < 16) accA += d; else accB += d;
    }
    accB = fma4(accB, v4, sw[lane + 16]);
    accB = fma4(accB, v5, sw[lane + 48]);
    accB = fma4(accB, v6, sw[lane + 80]);

    // Two interleaved butterfly reductions.
#pragma unroll
    for (int o = 16; o > 0; o >>= 1) {
        accA += __shfl_xor_sync(0xFFFFFFFFu, accA, o);
        accB += __shfl_xor_sync(0xFFFFFFFFu, accB, o);
    }

    if (lane < ROWS_PER_WARP && n0 + lane < n_rows) {
        float r = (lane == 0) ? accA : accB;
        y[n0 + lane] = beta0_p[0] + r;
    }
}

extern "C" void kernel_launch(void* const* d_in, const int* in_sizes, int n_in,
                              void* d_out, int out_size)
{
    const float* x     = (const float*)d_in[0];
    const float* beta0 = (const float*)d_in[1];
    const float* gamma = (const float*)d_in[2];
    const float* alpha = (const float*)d_in[3];
    float* y = (float*)d_out;

    int n_rows = in_sizes[0] / W_ELEMS;

    prep_w_kernel<<<N_GAMMA, N_ALPHA>>>(gamma, alpha);

    int rows_per_block = WARPS_PER_BLOCK * ROWS_PER_WARP;  // 16
    int grid = (n_rows + rows_per_block - 1) / rows_per_block;

    cudaLaunchConfig_t cfg = {};
    cfg.gridDim  = dim3(grid, 1, 1);
    cfg.blockDim = dim3(256, 1, 1);
    cfg.dynamicSmemBytes = 0;
    cfg.stream = 0;
    cudaLaunchAttribute attrs[1];
    attrs[0].id = cudaLaunchAttributeProgrammaticStreamSerialization;
    attrs[0].val.programmaticStreamSerializationAllowed = 1;
    cfg.attrs = attrs;
    cfg.numAttrs = 1;

    cudaError_t err = cudaLaunchKernelEx(&cfg, cp_dot_kernel, x, beta0, y, n_rows);
    if (err != cudaSuccess) {
        cp_dot_kernel<<<grid, 256>>>(x, beta0, y, n_rows);
    }
}